// round 3
// baseline (speedup 1.0000x reference)
#include <cuda_runtime.h>
#include <mma.h>
#include <cstdint>
using namespace nvcuda;

#define EPSV 1e-5f

__device__ float g_S[32*4096];
__device__ float g_colsum[2048];
__device__ float g_wm[32*4096];
__device__ float g_mean[2048];
__device__ float g_svw[4096];
__device__ float g_svm[64];
__device__ float g_A[32*4096];
__device__ float g_bp[2048];

// ---------------- K0: zero atomic accumulators (every replay) ----------------
__global__ void k0_zero() {
    int i = blockIdx.x * 256 + threadIdx.x;
    g_S[i] = 0.f;
    if (i < 2048) g_colsum[i] = 0.f;
}

// ---------------- K1: tf32 Gram (X X^T) + column sums ------------------------
// grid (16 slices, 32 batches), 256 threads. Each block: 64 rows x 1024 cols.
__global__ __launch_bounds__(256) void k1_gram(const float* __restrict__ x,
                                               const int* __restrict__ idx) {
    __shared__ float Xs[64][36];
    __shared__ float Ssm[4096];
    __shared__ const float* rowp[64];
    int sl = blockIdx.x, b = blockIdx.y, t = threadIdx.x;
    if (t < 64)
        rowp[t] = x + ((size_t)(b * 256 + idx[4 * t + (sl >> 2)])) * 4096 + (sl & 3) * 1024;
    int w = t >> 5, rw = w & 3, cw = (w >> 2) * 2;
    wmma::fragment<wmma::accumulator, 16, 16, 8, float> acc0, acc1;
    wmma::fill_fragment(acc0, 0.f);
    wmma::fill_fragment(acc1, 0.f);
    int lr = t >> 3, lc = (t & 7) * 4;
    float cs0 = 0.f, cs1 = 0.f;
    __syncthreads();
    for (int kc = 0; kc < 32; kc++) {
        float4 v0 = *(const float4*)(rowp[lr] + kc * 32 + lc);
        float4 v1 = *(const float4*)(rowp[lr + 32] + kc * 32 + lc);
        cs0 += v0.x + v0.y + v0.z + v0.w;
        cs1 += v1.x + v1.y + v1.z + v1.w;
        __syncthreads();  // prior mma reads of Xs complete
        Xs[lr][lc + 0] = wmma::__float_to_tf32(v0.x);
        Xs[lr][lc + 1] = wmma::__float_to_tf32(v0.y);
        Xs[lr][lc + 2] = wmma::__float_to_tf32(v0.z);
        Xs[lr][lc + 3] = wmma::__float_to_tf32(v0.w);
        Xs[lr + 32][lc + 0] = wmma::__float_to_tf32(v1.x);
        Xs[lr + 32][lc + 1] = wmma::__float_to_tf32(v1.y);
        Xs[lr + 32][lc + 2] = wmma::__float_to_tf32(v1.z);
        Xs[lr + 32][lc + 3] = wmma::__float_to_tf32(v1.w);
        __syncthreads();
#pragma unroll
        for (int kk = 0; kk < 4; kk++) {
            wmma::fragment<wmma::matrix_a, 16, 16, 8, wmma::precision::tf32, wmma::row_major> af;
            wmma::fragment<wmma::matrix_b, 16, 16, 8, wmma::precision::tf32, wmma::col_major> b0, b1;
            wmma::load_matrix_sync(af, &Xs[rw * 16][kk * 8], 36);
            wmma::load_matrix_sync(b0, &Xs[cw * 16][kk * 8], 36);
            wmma::load_matrix_sync(b1, &Xs[(cw + 1) * 16][kk * 8], 36);
            wmma::mma_sync(acc0, af, b0, acc0);
            wmma::mma_sync(acc1, af, b1, acc1);
        }
    }
    wmma::store_matrix_sync(&Ssm[(rw * 16) * 64 + cw * 16], acc0, 64, wmma::mem_row_major);
    wmma::store_matrix_sync(&Ssm[(rw * 16) * 64 + (cw + 1) * 16], acc1, 64, wmma::mem_row_major);
#pragma unroll
    for (int d = 4; d > 0; d >>= 1) {
        cs0 += __shfl_down_sync(0xffffffffu, cs0, d, 8);
        cs1 += __shfl_down_sync(0xffffffffu, cs1, d, 8);
    }
    if ((t & 7) == 0) {
        atomicAdd(&g_colsum[b * 64 + lr], cs0);
        atomicAdd(&g_colsum[b * 64 + lr + 32], cs1);
    }
    __syncthreads();
#pragma unroll
    for (int i = 0; i < 16; i++)
        atomicAdd(&g_S[b * 4096 + t + 256 * i], Ssm[t + 256 * i]);
}

// ------------- shared 64x64 smem matmul, LD=65, 256 threads ------------------
__device__ __forceinline__ void mm64x(const float* __restrict__ A,
                                      const float* __restrict__ B,
                                      float* __restrict__ C, int t, bool fin) {
    int r0 = (t >> 4) << 2, c0 = t & 15;
    float acc[16];
#pragma unroll
    for (int i = 0; i < 16; i++) acc[i] = 0.f;
#pragma unroll 8
    for (int k = 0; k < 64; k++) {
        float a0 = A[(r0 + 0) * 65 + k], a1 = A[(r0 + 1) * 65 + k];
        float a2 = A[(r0 + 2) * 65 + k], a3 = A[(r0 + 3) * 65 + k];
        float b0 = B[k * 65 + c0],      b1 = B[k * 65 + c0 + 16];
        float b2 = B[k * 65 + c0 + 32], b3 = B[k * 65 + c0 + 48];
        acc[0] += a0*b0; acc[1] += a0*b1; acc[2]  += a0*b2; acc[3]  += a0*b3;
        acc[4] += a1*b0; acc[5] += a1*b1; acc[6]  += a1*b2; acc[7]  += a1*b3;
        acc[8] += a2*b0; acc[9] += a2*b1; acc[10] += a2*b2; acc[11] += a2*b3;
        acc[12]+= a3*b0; acc[13]+= a3*b1; acc[14] += a3*b2; acc[15] += a3*b3;
    }
#pragma unroll
    for (int i = 0; i < 4; i++)
#pragma unroll
        for (int j = 0; j < 4; j++) {
            int ci = (r0 + i) * 65 + c0 + 16 * j;
            C[ci] = fin ? (1.5f * A[ci] - 0.5f * acc[i * 4 + j]) : acc[i * 4 + j];
        }
}

// ---------------- K2a: sigma -> Newton-Schulz -> wm (fp32) -------------------
__global__ __launch_bounds__(256) void k2a_ns() {
    extern __shared__ float sm[];
    float* sigN = sm;
    float* bA = sm + 4160;
    float* bB = sm + 8320;
    float* bC = sm + 12480;
    __shared__ float smean[64];
    __shared__ float s_tr;
    int b = blockIdx.x, t = threadIdx.x;
    if (t < 64) smean[t] = g_colsum[b * 64 + t] * (1.f / 16384.f);
    if (t == 0) s_tr = 0.f;
    __syncthreads();
#pragma unroll
    for (int i = 0; i < 16; i++) {
        int e = t + 256 * i, g = e >> 6, h = e & 63;
        sigN[g * 65 + h] = g_S[b * 4096 + e] * (1.f / 16384.f) - smean[g] * smean[h];
        bA[g * 65 + h] = (g == h) ? 1.f : 0.f;
    }
    __syncthreads();
    if (t < 64) atomicAdd(&s_tr, sigN[t * 65 + t]);
    __syncthreads();
    float trinv = 1.f / s_tr;
#pragma unroll
    for (int i = 0; i < 16; i++) {
        int e = t + 256 * i;
        sigN[(e >> 6) * 65 + (e & 63)] *= trinv;
    }
    __syncthreads();
    float *p = bA, *t1 = bB, *t2 = bC;
    for (int it = 0; it < 5; it++) {
        mm64x(p, sigN, t1, t, false); __syncthreads();  // T1 = P@sigN
        mm64x(p, t1, t2, t, false);   __syncthreads();  // T2 = P@T1
        mm64x(p, t2, t1, t, true);    __syncthreads();  // P' = 1.5P - 0.5*P@T2
        float* tmp = p; p = t1; t1 = tmp;
    }
    float sq = sqrtf(trinv);
#pragma unroll
    for (int i = 0; i < 16; i++) {
        int e = t + 256 * i;
        g_wm[b * 4096 + e] = p[(e >> 6) * 65 + (e & 63)] * sq;
    }
    if (t < 64) g_mean[b * 64 + t] = smean[t];
}

// ---------------- K2b: cross-batch sqrt-variance (ddof=1) --------------------
__global__ void k2b_var() {
    int e = blockIdx.x * 256 + threadIdx.x;
    if (e < 4096) {
        float v[32], mu = 0.f;
        for (int b = 0; b < 32; b++) { v[b] = g_wm[b * 4096 + e]; mu += v[b]; }
        mu *= (1.f / 32.f);
        float s = 0.f;
        for (int b = 0; b < 32; b++) { float d = v[b] - mu; s += d * d; }
        g_svw[e] = sqrtf(s * (1.f / 31.f) + EPSV);
    } else if (e < 4160) {
        int g = e - 4096;
        float v[32], mu = 0.f;
        for (int b = 0; b < 32; b++) { v[b] = g_mean[b * 64 + g]; mu += v[b]; }
        mu *= (1.f / 32.f);
        float s = 0.f;
        for (int b = 0; b < 32; b++) { float d = v[b] - mu; s += d * d; }
        g_svm[g] = sqrtf(s * (1.f / 31.f) + EPSV);
    }
}

// ---------------- K2c: gamma symmetrize, A = gamma@wm, beta' -----------------
__global__ __launch_bounds__(256) void k2c_gamma(const float* __restrict__ eps1,
                                                 const float* __restrict__ eps2) {
    extern __shared__ float sm[];
    float* W = sm;
    float* Gm = sm + 4160;
    float* Am = sm + 8320;
    __shared__ float smean[64];
    int b = blockIdx.x, t = threadIdx.x;
    if (t < 64) smean[t] = g_mean[b * 64 + t];
#pragma unroll
    for (int i = 0; i < 16; i++) {
        int e = t + 256 * i;
        W[(e >> 6) * 65 + (e & 63)] = g_wm[b * 4096 + e];
    }
    __syncthreads();
#pragma unroll
    for (int i = 0; i < 16; i++) {
        int e = t + 256 * i, g = e >> 6, h = e & 63;
        int gg = (g <= h) ? g : h, hh = (g <= h) ? h : g;
        Gm[g * 65 + h] = W[gg * 65 + hh] + eps1[b * 4096 + gg * 64 + hh] * g_svw[gg * 64 + hh];
    }
    __syncthreads();
    mm64x(Gm, W, Am, t, false);
    __syncthreads();
#pragma unroll
    for (int i = 0; i < 16; i++) {
        int e = t + 256 * i;
        g_A[b * 4096 + e] = Am[(e >> 6) * 65 + (e & 63)];
    }
    if (t < 64) {
        float s = 0.f;
        for (int h = 0; h < 64; h++) s += Am[t * 65 + h] * smean[h];
        g_bp[b * 64 + t] = smean[t] + eps2[b * 64 + t] * g_svm[t] - s;
    }
}

// ---------------- K3: y = A@xs + beta', tf32 wmma, permuted I/O --------------
// grid (16 slices, 32 batches), 256 threads; per block 64 rows x 1024 cols.
__global__ __launch_bounds__(256) void k3_apply(const float* __restrict__ x,
                                                const int* __restrict__ idx,
                                                float* __restrict__ out) {
    extern __shared__ float sm[];
    float* As = sm;             // 64 x 68 (tf32)
    float* Xs = sm + 64 * 68;   // 64 x 132
    __shared__ const float* inp[64];
    __shared__ float* outp[64];
    __shared__ float bps[64];
    int sl = blockIdx.x, b = blockIdx.y, t = threadIdx.x;
    if (t < 64) {
        size_t off = ((size_t)(b * 256 + idx[4 * t + (sl >> 2)])) * 4096 + (sl & 3) * 1024;
        inp[t] = x + off;
        outp[t] = out + off;
        bps[t] = g_bp[b * 64 + t];
    }
#pragma unroll
    for (int i = 0; i < 16; i++) {
        int e = t + 256 * i;
        As[(e >> 6) * 68 + (e & 63)] = wmma::__float_to_tf32(g_A[b * 4096 + e]);
    }
    __syncthreads();
    int w = t >> 5, rw = w & 3, cb = (w >> 2) * 4;
    int row = t >> 2, q = (t & 3) * 4;
    for (int cc = 0; cc < 1024; cc += 128) {
#pragma unroll
        for (int j = 0; j < 8; j++) {
            float4 v = *(const float4*)(inp[row] + cc + q + j * 16);
            int c = q + j * 16;
            Xs[row * 132 + c]     = wmma::__float_to_tf32(v.x);
            Xs[row * 132 + c + 1] = wmma::__float_to_tf32(v.y);
            Xs[row * 132 + c + 2] = wmma::__float_to_tf32(v.z);
            Xs[row * 132 + c + 3] = wmma::__float_to_tf32(v.w);
        }
        __syncthreads();
        wmma::fragment<wmma::accumulator, 16, 16, 8, float> acc[4];
#pragma unroll
        for (int j = 0; j < 4; j++) wmma::fill_fragment(acc[j], 0.f);
#pragma unroll
        for (int k0 = 0; k0 < 8; k0++) {
            wmma::fragment<wmma::matrix_a, 16, 16, 8, wmma::precision::tf32, wmma::row_major> af;
            wmma::load_matrix_sync(af, &As[(rw * 16) * 68 + k0 * 8], 68);
#pragma unroll
            for (int j = 0; j < 4; j++) {
                wmma::fragment<wmma::matrix_b, 16, 16, 8, wmma::precision::tf32, wmma::row_major> bf;
                wmma::load_matrix_sync(bf, &Xs[(k0 * 8) * 132 + (cb + j) * 16], 132);
                wmma::mma_sync(acc[j], af, bf, acc[j]);
            }
        }
        __syncthreads();  // done reading Xs; reuse it as output staging
#pragma unroll
        for (int j = 0; j < 4; j++)
            wmma::store_matrix_sync(&Xs[(rw * 16) * 132 + (cb + j) * 16], acc[j], 132,
                                    wmma::mem_row_major);
        __syncthreads();
        float bpv = bps[row];
#pragma unroll
        for (int j = 0; j < 8; j++) {
            int c = q + j * 16;
            float4 v = *(float4*)(&Xs[row * 132 + c]);
            v.x += bpv; v.y += bpv; v.z += bpv; v.w += bpv;
            *(float4*)(outp[row] + cc + c) = v;
        }
        __syncthreads();
    }
}

extern "C" void kernel_launch(void* const* d_in, const int* in_sizes, int n_in,
                              void* d_out, int out_size) {
    const float* x    = (const float*)d_in[0];
    const int*   idx  = (const int*)d_in[1];
    const float* eps1 = (const float*)d_in[2];
    const float* eps2 = (const float*)d_in[3];
    float* out = (float*)d_out;
    cudaFuncSetAttribute(k2a_ns,    cudaFuncAttributeMaxDynamicSharedMemorySize, 66560);
    cudaFuncSetAttribute(k2c_gamma, cudaFuncAttributeMaxDynamicSharedMemorySize, 49920);
    cudaFuncSetAttribute(k3_apply,  cudaFuncAttributeMaxDynamicSharedMemorySize, 51200);
    k0_zero<<<512, 256>>>();
    k1_gram<<<dim3(16, 32), 256>>>(x, idx);
    k2a_ns<<<32, 256, 66560>>>();
    k2b_var<<<17, 256>>>();
    k2c_gamma<<<32, 256, 49920>>>(eps1, eps2);
    k3_apply<<<dim3(16, 32), 256, 51200>>>(x, idx, out);
}